// round 5
// baseline (speedup 1.0000x reference)
#include <cuda_runtime.h>

// Shapes (fixed)
#define BB 256
#define NN 16
#define OBS 64
#define ACT 8
#define DD 128
#define HH 64
#define II 72
#define NF 192

// 16B-aligned padded strides (floats)
#define WE_S 76
#define W1_S 196
#define ST_S 68
#define AC_S 12
#define E_S  132
#define WT_S 17
#define HV_S 68

// float offsets into dynamic smem (all float4-aligned)
#define OFF_WEU 0
#define SZ_WEU  12544                 /* max(128*76=9728, 64*196=12544) */
#define OFF_WA  (OFF_WEU + SZ_WEU)
#define OFF_W2  (OFF_WA + 2 * DD)
#define OFF_ST  (OFF_W2 + HH)
#define OFF_AC  (OFF_ST + NN * ST_S)
#define OFF_PO  (OFF_AC + NN * AC_S)
#define OFF_TA  (OFF_PO + NN * AC_S)
#define OFF_DE  (OFF_TA + NN * E_S)
#define OFF_W   (OFF_DE + NN * E_S)
#define OFF_T   (OFF_W  + NN * WT_S)
#define OFF_V   (OFF_T  + NN * HV_S)
#define OFF_U   (OFF_V  + NN * HV_S)
#define OFF_SSRC (OFF_U + NN * HV_S)
#define OFF_SDST (OFF_SSRC + NN)
#define SMEM_FLOATS (OFF_SDST + NN)

typedef unsigned long long u64;

__device__ __forceinline__ float lrelu(float x) {
    return fmaxf(x, 0.01f * x);
}

__device__ __forceinline__ float fast_tanh(float x) {
    float cx = fminf(fmaxf(x, -10.0f), 10.0f);
    float e = __expf(2.0f * cx);
    return __fdividef(e - 1.0f, e + 1.0f);
}

__device__ __forceinline__ float dot4(float4 a, float4 b, float acc) {
    acc = fmaf(a.x, b.x, acc);
    acc = fmaf(a.y, b.y, acc);
    acc = fmaf(a.z, b.z, acc);
    acc = fmaf(a.w, b.w, acc);
    return acc;
}

// packed fp32x2 FMA (sm_100+; ptxas never auto-fuses this)
__device__ __forceinline__ u64 fma2(u64 a, u64 b, u64 c) {
    u64 d;
    asm("fma.rn.f32x2 %0, %1, %2, %3;" : "=l"(d) : "l"(a), "l"(b), "l"(c));
    return d;
}
__device__ __forceinline__ float hadd2(u64 v) {
    float lo, hi;
    asm("mov.b64 {%0, %1}, %2;" : "=f"(lo), "=f"(hi) : "l"(v));
    return lo + hi;
}

__global__ void __launch_bounds__(256, 2)
gac_kernel(const float* __restrict__ g_st, const float* __restrict__ g_po,
           const float* __restrict__ g_ac, const float* __restrict__ g_We,
           const float* __restrict__ g_Wa, const float* __restrict__ g_W1,
           const float* __restrict__ g_W2, float* __restrict__ out,
           int write_w)
{
    extern __shared__ float sm[];
    float* We  = sm + OFF_WEU;   // [128][76] phase 1
    float* W1  = sm + OFF_WEU;   // [64][196] phase 3+ (union)
    float* Wa  = sm + OFF_WA;
    float* W2s = sm + OFF_W2;
    float* st  = sm + OFF_ST;
    float* ac  = sm + OFF_AC;
    float* po  = sm + OFF_PO;
    float* ta  = sm + OFF_TA;
    float* de  = sm + OFF_DE;
    float* w   = sm + OFF_W;
    float* T   = sm + OFF_T;
    float* V   = sm + OFF_V;
    float* U   = sm + OFF_U;
    float* ssrc = sm + OFF_SSRC;
    float* sdst = sm + OFF_SDST;

    const int t = threadIdx.x;
    const int b = blockIdx.x;

    // ---- P0: cooperative float4 loads ----
    {
        #pragma unroll
        for (int i = 0; i < 9; i++) {
            int e = (t + i * 256) * 4;
            int r = e / II, c = e - r * II;
            float4 v = *(const float4*)&g_We[e];
            *(float4*)&We[r * WE_S + c] = v;
        }
        if (t < 64) *(float4*)&Wa[t * 4] = *(const float4*)&g_Wa[t * 4];
        if (t < 16) *(float4*)&W2s[t * 4] = *(const float4*)&g_W2[t * 4];
        {
            int r = t >> 4, c = (t & 15) * 4;
            *(float4*)&st[r * ST_S + c] = *(const float4*)&g_st[b * NN * OBS + t * 4];
        }
        if (t < 32) {
            int r = t >> 1, c = (t & 1) * 4;
            *(float4*)&ac[r * AC_S + c] = *(const float4*)&g_ac[b * NN * ACT + t * 4];
            *(float4*)&po[r * AC_S + c] = *(const float4*)&g_po[b * NN * ACT + t * 4];
        }
        if (t < NN) { ssrc[t] = 0.0f; sdst[t] = 0.0f; }
    }
    __syncthreads();

    // ---- P1: embeddings, 2n x 4d tiles, f32x2 inner math ----
    {
        const int np = t & 7;
        const int n0 = np * 2, n1 = n0 + 1;
        const int d0 = (t >> 3) * 4;

        u64 sa0[4], sa1[4], sp0[4], sp1[4];
        #pragma unroll
        for (int u = 0; u < 4; u++) { sa0[u] = 0ull; sa1[u] = 0ull; }
        #pragma unroll
        for (int k = 0; k < OBS; k += 4) {
            ulonglong2 x0 = *(const ulonglong2*)&st[n0 * ST_S + k];
            ulonglong2 x1 = *(const ulonglong2*)&st[n1 * ST_S + k];
            #pragma unroll
            for (int u = 0; u < 4; u++) {
                ulonglong2 wv = *(const ulonglong2*)&We[(d0 + u) * WE_S + k];
                sa0[u] = fma2(wv.x, x0.x, sa0[u]);
                sa0[u] = fma2(wv.y, x0.y, sa0[u]);
                sa1[u] = fma2(wv.x, x1.x, sa1[u]);
                sa1[u] = fma2(wv.y, x1.y, sa1[u]);
            }
        }
        #pragma unroll
        for (int u = 0; u < 4; u++) { sp0[u] = sa0[u]; sp1[u] = sa1[u]; }
        #pragma unroll
        for (int k = 0; k < ACT; k += 4) {
            ulonglong2 xa0 = *(const ulonglong2*)&ac[n0 * AC_S + k];
            ulonglong2 xa1 = *(const ulonglong2*)&ac[n1 * AC_S + k];
            ulonglong2 xp0 = *(const ulonglong2*)&po[n0 * AC_S + k];
            ulonglong2 xp1 = *(const ulonglong2*)&po[n1 * AC_S + k];
            #pragma unroll
            for (int u = 0; u < 4; u++) {
                ulonglong2 wv = *(const ulonglong2*)&We[(d0 + u) * WE_S + OBS + k];
                sa0[u] = fma2(wv.x, xa0.x, sa0[u]);
                sa0[u] = fma2(wv.y, xa0.y, sa0[u]);
                sa1[u] = fma2(wv.x, xa1.x, sa1[u]);
                sa1[u] = fma2(wv.y, xa1.y, sa1[u]);
                sp0[u] = fma2(wv.x, xp0.x, sp0[u]);
                sp0[u] = fma2(wv.y, xp0.y, sp0[u]);
                sp1[u] = fma2(wv.x, xp1.x, sp1[u]);
                sp1[u] = fma2(wv.y, xp1.y, sp1[u]);
            }
        }
        // horizontal add -> scalar pre-activation embeddings
        float ea0[4], ea1[4], ep0[4], ep1[4];
        #pragma unroll
        for (int u = 0; u < 4; u++) {
            ea0[u] = hadd2(sa0[u]); ea1[u] = hadd2(sa1[u]);
            ep0[u] = hadd2(sp0[u]); ep1[u] = hadd2(sp1[u]);
        }
        // attention-scalar partials
        float4 wsrc = *(const float4*)&Wa[d0];
        float4 wdst = *(const float4*)&Wa[DD + d0];
        float4 a0 = make_float4(ea0[0], ea0[1], ea0[2], ea0[3]);
        float4 a1 = make_float4(ea1[0], ea1[1], ea1[2], ea1[3]);
        float ps0 = dot4(wsrc, a0, 0.0f), ps1 = dot4(wsrc, a1, 0.0f);
        float pd0 = dot4(wdst, a0, 0.0f), pd1 = dot4(wdst, a1, 0.0f);
        // tanh + delta, float4 stores
        {
            float4 t0, t1, dd0, dd1;
            t0.x = fast_tanh(ea0[0]); t0.y = fast_tanh(ea0[1]);
            t0.z = fast_tanh(ea0[2]); t0.w = fast_tanh(ea0[3]);
            t1.x = fast_tanh(ea1[0]); t1.y = fast_tanh(ea1[1]);
            t1.z = fast_tanh(ea1[2]); t1.w = fast_tanh(ea1[3]);
            dd0.x = fast_tanh(ep0[0]) - t0.x; dd0.y = fast_tanh(ep0[1]) - t0.y;
            dd0.z = fast_tanh(ep0[2]) - t0.z; dd0.w = fast_tanh(ep0[3]) - t0.w;
            dd1.x = fast_tanh(ep1[0]) - t1.x; dd1.y = fast_tanh(ep1[1]) - t1.y;
            dd1.z = fast_tanh(ep1[2]) - t1.z; dd1.w = fast_tanh(ep1[3]) - t1.w;
            *(float4*)&ta[n0 * E_S + d0] = t0;
            *(float4*)&ta[n1 * E_S + d0] = t1;
            *(float4*)&de[n0 * E_S + d0] = dd0;
            *(float4*)&de[n1 * E_S + d0] = dd1;
        }
        // reduce partials over the 4 lanes sharing np
        ps0 += __shfl_xor_sync(0xffffffffu, ps0, 8);
        ps0 += __shfl_xor_sync(0xffffffffu, ps0, 16);
        ps1 += __shfl_xor_sync(0xffffffffu, ps1, 8);
        ps1 += __shfl_xor_sync(0xffffffffu, ps1, 16);
        pd0 += __shfl_xor_sync(0xffffffffu, pd0, 8);
        pd0 += __shfl_xor_sync(0xffffffffu, pd0, 16);
        pd1 += __shfl_xor_sync(0xffffffffu, pd1, 8);
        pd1 += __shfl_xor_sync(0xffffffffu, pd1, 16);
        if ((t & 31) < 8) {
            atomicAdd(&ssrc[n0], ps0);
            atomicAdd(&ssrc[n1], ps1);
            atomicAdd(&sdst[n0], pd0);
            atomicAdd(&sdst[n1], pd1);
        }
    }
    __syncthreads();

    // ---- P2: parallel softmax (all threads) + W1 float4 load ----
    {
        const int i = t >> 4, j = t & 15;
        float e = lrelu(ssrc[i] + sdst[j]);
        float mx = e;
        #pragma unroll
        for (int m = 8; m; m >>= 1)
            mx = fmaxf(mx, __shfl_xor_sync(0xffffffffu, mx, m));
        float ex = __expf(e - mx);
        float sum = ex;
        #pragma unroll
        for (int m = 8; m; m >>= 1)
            sum += __shfl_xor_sync(0xffffffffu, sum, m);
        float wv = __fdividef(ex, sum);
        w[i * WT_S + j] = wv;
        if (write_w)
            out[BB * NN * NN + b * NN * NN + t] = wv;
    }
    #pragma unroll
    for (int i = 0; i < 12; i++) {
        int e = (t + i * 256) * 4;
        int r = e / NF, c = e - r * NF;
        float4 v = *(const float4*)&g_W1[e];
        *(float4*)&W1[r * W1_S + c] = v;
    }
    __syncthreads();

    // ---- P3: T/V/au via f32x2 ----
    const int pn = t & 15, ph0 = (t >> 4) * 4;
    float auf[4];
    {
        u64 at[4], av[4], au[4];
        #pragma unroll
        for (int u = 0; u < 4; u++) { at[u] = 0ull; av[u] = 0ull; au[u] = 0ull; }
        #pragma unroll
        for (int k = 0; k < OBS; k += 4) {
            ulonglong2 x = *(const ulonglong2*)&st[pn * ST_S + k];
            #pragma unroll
            for (int u = 0; u < 4; u++) {
                ulonglong2 wv = *(const ulonglong2*)&W1[(ph0 + u) * W1_S + k];
                au[u] = fma2(wv.x, x.x, au[u]);
                au[u] = fma2(wv.y, x.y, au[u]);
            }
        }
        #pragma unroll
        for (int d = 0; d < DD; d += 4) {
            ulonglong2 xt = *(const ulonglong2*)&ta[pn * E_S + d];
            ulonglong2 xd = *(const ulonglong2*)&de[pn * E_S + d];
            #pragma unroll
            for (int u = 0; u < 4; u++) {
                ulonglong2 wv = *(const ulonglong2*)&W1[(ph0 + u) * W1_S + OBS + d];
                at[u] = fma2(wv.x, xt.x, at[u]);
                at[u] = fma2(wv.y, xt.y, at[u]);
                av[u] = fma2(wv.x, xd.x, av[u]);
                av[u] = fma2(wv.y, xd.y, av[u]);
            }
        }
        const float invN = 1.0f / 16.0f;
        float4 tv, vv;
        tv.x = hadd2(at[0]) * invN; tv.y = hadd2(at[1]) * invN;
        tv.z = hadd2(at[2]) * invN; tv.w = hadd2(at[3]) * invN;
        vv.x = hadd2(av[0]) * invN; vv.y = hadd2(av[1]) * invN;
        vv.z = hadd2(av[2]) * invN; vv.w = hadd2(av[3]) * invN;
        auf[0] = hadd2(au[0]); auf[1] = hadd2(au[1]);
        auf[2] = hadd2(au[2]); auf[3] = hadd2(au[3]);
        *(float4*)&T[pn * HV_S + ph0] = tv;
        *(float4*)&V[pn * HV_S + ph0] = vv;
    }
    __syncthreads();

    // ---- P4a: U[n,h] = au + sum_j w[n,j] * T[j,h] ----
    {
        float acc[4];
        #pragma unroll
        for (int u = 0; u < 4; u++) acc[u] = auf[u];
        #pragma unroll
        for (int j = 0; j < NN; j++) {
            float wv = w[pn * WT_S + j];
            float4 tv = *(const float4*)&T[j * HV_S + ph0];
            acc[0] = fmaf(wv, tv.x, acc[0]);
            acc[1] = fmaf(wv, tv.y, acc[1]);
            acc[2] = fmaf(wv, tv.z, acc[2]);
            acc[3] = fmaf(wv, tv.w, acc[3]);
        }
        float4 uv;
        uv.x = acc[0]; uv.y = acc[1]; uv.z = acc[2]; uv.w = acc[3];
        *(float4*)&U[pn * HV_S + ph0] = uv;
    }
    __syncthreads();

    // ---- P4b: value[b,i,j] = W2 . lrelu(U[i] + w[i,j]*V[j]) ----
    {
        const int i = t >> 4, j = t & 15;
        float wv = w[i * WT_S + j];
        float acc = 0.0f;
        #pragma unroll
        for (int h = 0; h < HH; h += 4) {
            float4 u4 = *(const float4*)&U[i * HV_S + h];
            float4 v4 = *(const float4*)&V[j * HV_S + h];
            float4 w2 = *(const float4*)&W2s[h];
            acc = fmaf(w2.x, lrelu(fmaf(wv, v4.x, u4.x)), acc);
            acc = fmaf(w2.y, lrelu(fmaf(wv, v4.y, u4.y)), acc);
            acc = fmaf(w2.z, lrelu(fmaf(wv, v4.z, u4.z)), acc);
            acc = fmaf(w2.w, lrelu(fmaf(wv, v4.w, u4.w)), acc);
        }
        out[b * NN * NN + t] = acc;
    }
}

extern "C" void kernel_launch(void* const* d_in, const int* in_sizes, int n_in,
                              void* d_out, int out_size) {
    const float* st = (const float*)d_in[0];
    const float* po = (const float*)d_in[1];
    const float* ac = (const float*)d_in[2];
    const float* We = (const float*)d_in[3];
    const float* Wa = (const float*)d_in[4];
    const float* W1 = (const float*)d_in[5];
    const float* W2 = (const float*)d_in[6];
    float* out = (float*)d_out;

    const int smem = SMEM_FLOATS * (int)sizeof(float);
    cudaFuncSetAttribute(gac_kernel, cudaFuncAttributeMaxDynamicSharedMemorySize, smem);

    int write_w = (out_size >= 2 * BB * NN * NN) ? 1 : 0;

    gac_kernel<<<BB, 256, smem>>>(st, po, ac, We, Wa, W1, W2, out, write_w);
}